// round 1
// baseline (speedup 1.0000x reference)
#include <cuda_runtime.h>

// BlurModel: 100x100 box filter (x 1e-4), VALID, then threshold >0.129 -> 1.0.
// Input  x: [8,3,1024,1024] f32  (flattened as 24 images of 1024x1024)
// Output  : [8,3,925,925]  f32
//
// Separable: vertical 100-sum (pass A, thread-per-column sliding window),
// then horizontal 100-sum via per-row inclusive prefix in smem (pass B),
// scaled by 1e-4 and thresholded.

#define IMGS 24
#define H    1024
#define W    1024
#define KS   100
#define OH   925   // 1024 - 99
#define OW   925
#define CHUNK 128  // output rows per pass-A block

// Scratch: vertical box sums, width still 1024. 24*925*1024*4B = 90.9 MB.
__device__ float g_tmp[(size_t)IMGS * OH * W];

// ---------------- Pass A: vertical sliding 100-sum ----------------
// grid: (4 col-blocks, ceil(925/CHUNK), 24 imgs), block: 256 threads.
// Thread owns one column; warp reads are 128B-contiguous (fully coalesced).
__global__ __launch_bounds__(256) void vpass(const float* __restrict__ x) {
    const int c   = blockIdx.x * 256 + threadIdx.x;   // column 0..1023
    const int img = blockIdx.z;
    const int r0  = blockIdx.y * CHUNK;
    const int rend = min(r0 + CHUNK, OH);

    const float* __restrict__ in  = x     + (size_t)img * H  * W;
    float*       __restrict__ out = g_tmp + (size_t)img * OH * W;

    // initial window: rows [r0, r0+99]
    float s = 0.f;
    #pragma unroll 5
    for (int k = 0; k < KS; ++k)
        s += in[(size_t)(r0 + k) * W + c];
    out[(size_t)r0 * W + c] = s;

    // slide: add row r+99, subtract row r-1 (subtract re-read hits L1/L2)
    for (int r = r0 + 1; r < rend; ++r) {
        s += in[(size_t)(r + KS - 1) * W + c] - in[(size_t)(r - 1) * W + c];
        out[(size_t)r * W + c] = s;
    }
}

// ---------------- Pass B: horizontal 100-sum via row prefix ----------------
// grid: (925 rows, 24 imgs), block: 256 threads. One block per row.
// Load 1024 floats (float4, coalesced) -> block inclusive prefix in smem ->
// out[j] = P[j+99] - P[j-1], scale, threshold, coalesced store of 925 floats.
__global__ __launch_bounds__(256) void hpass(float* __restrict__ out) {
    __shared__ float sp[W];        // inclusive prefix of the row
    __shared__ float warpsum[8];

    const int tid  = threadIdx.x;
    const int lane = tid & 31;
    const int warp = tid >> 5;
    const int row  = blockIdx.x;
    const int img  = blockIdx.y;

    const float4* __restrict__ rowp =
        (const float4*)(g_tmp + ((size_t)img * OH + row) * W);
    float4 v = rowp[tid];

    // serial prefix of the 4-element chunk
    float p0 = v.x;
    float p1 = p0 + v.y;
    float p2 = p1 + v.z;
    float p3 = p2 + v.w;

    // warp inclusive scan of chunk totals
    float t = p3;
    #pragma unroll
    for (int d = 1; d < 32; d <<= 1) {
        float n = __shfl_up_sync(0xffffffffu, t, d);
        if (lane >= d) t += n;
    }
    if (lane == 31) warpsum[warp] = t;
    __syncthreads();

    if (warp == 0 && lane < 8) {
        float wv = warpsum[lane];
        #pragma unroll
        for (int d = 1; d < 8; d <<= 1) {
            float n = __shfl_up_sync(0xffu, wv, d);
            if (lane >= d) wv += n;
        }
        warpsum[lane] = wv;   // inclusive scan of warp totals
    }
    __syncthreads();

    const float base = (warp ? warpsum[warp - 1] : 0.f) + (t - p3); // thread-exclusive
    sp[4 * tid + 0] = base + p0;
    sp[4 * tid + 1] = base + p1;
    sp[4 * tid + 2] = base + p2;
    sp[4 * tid + 3] = base + p3;
    __syncthreads();

    float* __restrict__ orow = out + ((size_t)img * OH + row) * OW;
    #pragma unroll
    for (int j = tid; j < OW; j += 256) {
        float s = sp[j + KS - 1] - (j ? sp[j - 1] : 0.f);
        float o = s * 1e-4f;
        orow[j] = (o > 0.129f) ? 1.0f : o;
    }
}

extern "C" void kernel_launch(void* const* d_in, const int* in_sizes, int n_in,
                              void* d_out, int out_size) {
    (void)in_sizes; (void)n_in; (void)out_size;
    const float* x  = (const float*)d_in[0];
    float* out      = (float*)d_out;

    dim3 gA(W / 256, (OH + CHUNK - 1) / CHUNK, IMGS);   // 4 x 8 x 24 = 768 blocks
    vpass<<<gA, 256>>>(x);

    dim3 gB(OH, IMGS);                                  // 925 x 24 blocks
    hpass<<<gB, 256>>>(out);
}

// round 2
// speedup vs baseline: 1.1579x; 1.1579x over previous
#include <cuda_runtime.h>

// BlurModel: 100x100 box filter (x 1e-4), VALID, threshold >0.129 -> 1.0.
// Input  x: [8,3,1024,1024] f32  (24 images of 1024x1024)
// Output  : [8,3,925,925]  f32
//
// Fully fused separable filter, no global intermediate:
//   - block = (row-chunk, image), full 1024-col width
//   - vertical sliding 100-sums live in registers (2 cols/thread, 512 thr)
//   - per output row: block prefix scan in smem -> horizontal 100-sum by
//     difference -> scale -> threshold -> store
//   - next row's add/sub input loads are prefetched before the scan.

#define IMGS   24
#define H      1024
#define W      1024
#define KS     100
#define OH     925          // 1024 - 99
#define OW     925
#define RC     74           // output rows per block
#define NCHUNK 13           // ceil(925/74)
#define NT     512          // threads per block (2 columns each)

__global__ __launch_bounds__(NT) void blur_fused(const float* __restrict__ x,
                                                 float* __restrict__ out) {
    __shared__ float sp[W];          // inclusive prefix of vertical sums
    __shared__ float warpsum[NT / 32];

    const int tid  = threadIdx.x;
    const int lane = tid & 31;
    const int warp = tid >> 5;
    const int img  = blockIdx.y;
    const int r0   = blockIdx.x * RC;
    const int rend = min(r0 + RC, OH);

    const float2* __restrict__ inp =
        (const float2*)(x + (size_t)img * H * W);   // row*(W/2) + tid

    // ---- init vertical window: rows [r0, r0+99], accumulators in registers
    float a0 = 0.f, a1 = 0.f;
    #pragma unroll 4
    for (int k = 0; k < KS; ++k) {
        float2 v = inp[(size_t)(r0 + k) * (W / 2) + tid];
        a0 += v.x;
        a1 += v.y;
    }

    // prefetch add/sub rows for the second output row
    float2 addv = make_float2(0.f, 0.f), subv = make_float2(0.f, 0.f);
    if (r0 + 1 < rend) {
        addv = inp[(size_t)(r0 + KS) * (W / 2) + tid];
        subv = inp[(size_t)r0 * (W / 2) + tid];
    }

    for (int r = r0; r < rend; ++r) {
        if (r > r0) {
            a0 += addv.x - subv.x;
            a1 += addv.y - subv.y;
            if (r + 1 < rend) {   // prefetch next row pair; overlaps the scan
                addv = inp[(size_t)(r + KS) * (W / 2) + tid];
                subv = inp[(size_t)r * (W / 2) + tid];
            }
        }

        // ---- block inclusive prefix over the 1024 vertical sums
        float p1 = a0 + a1;       // thread-local total (2 elems)
        float t  = p1;
        #pragma unroll
        for (int d = 1; d < 32; d <<= 1) {
            float n = __shfl_up_sync(0xffffffffu, t, d);
            if (lane >= d) t += n;
        }
        if (lane == 31) warpsum[warp] = t;
        __syncthreads();

        if (warp == 0 && lane < NT / 32) {
            float wv = warpsum[lane];
            #pragma unroll
            for (int d = 1; d < NT / 32; d <<= 1) {
                float n = __shfl_up_sync(0xffffu, wv, d);
                if (lane >= d) wv += n;
            }
            warpsum[lane] = wv;
        }
        __syncthreads();

        const float base = (warp ? warpsum[warp - 1] : 0.f) + (t - p1);
        sp[2 * tid + 0] = base + a0;
        sp[2 * tid + 1] = base + p1;
        __syncthreads();

        // ---- horizontal 100-sum by prefix difference, scale, threshold
        float* __restrict__ orow = out + ((size_t)img * OH + r) * OW;
        #pragma unroll
        for (int j = tid; j < OW; j += NT) {
            float s = sp[j + KS - 1] - (j ? sp[j - 1] : 0.f);
            float o = s * 1e-4f;
            orow[j] = (o > 0.129f) ? 1.0f : o;
        }
        __syncthreads();   // sp/warpsum reuse next row
    }
}

extern "C" void kernel_launch(void* const* d_in, const int* in_sizes, int n_in,
                              void* d_out, int out_size) {
    (void)in_sizes; (void)n_in; (void)out_size;
    const float* x = (const float*)d_in[0];
    float* out     = (float*)d_out;

    dim3 grid(NCHUNK, IMGS);     // 13 x 24 = 312 blocks
    blur_fused<<<grid, NT>>>(x, out);
}

// round 4
// speedup vs baseline: 1.2498x; 1.0794x over previous
#include <cuda_runtime.h>

// BlurModel: 100x100 box filter (x 1e-4), VALID, threshold >0.129 -> 1.0.
// Input  x: [8,3,1024,1024] f32 (24 images), output [8,3,925,925] f32.
//
// Fused separable filter, 4 output rows per scan group:
//   - vertical sliding 100-sums in registers (2 cols/thread, 512 threads)
//   - per group of 4 rows: 4 concurrent block prefix scans (shared barriers)
//   - horizontal 100-sum by prefix difference, scale, threshold, store
//   - next group's add/sub input rows prefetched before the scan phase.

#define IMGS   24
#define H      1024
#define W      1024
#define W2     (W / 2)
#define KS     100
#define OH     925
#define OW     925
#define RC     76           // rows per block (19 groups of 4)
#define NG     (RC / 4)
#define NCHUNK 13
#define NT     512

__global__ __launch_bounds__(NT) void blur_fused4(const float* __restrict__ x,
                                                  float* __restrict__ out) {
    __shared__ float sp[4][W];            // 4 row prefixes, 16 KB
    __shared__ float warpsum[4][NT / 32];

    const int tid  = threadIdx.x;
    const int lane = tid & 31;
    const int warp = tid >> 5;
    const int img  = blockIdx.y;
    int r0 = blockIdx.x * RC;
    if (r0 > OH - RC) r0 = OH - RC;       // uniform chunks; overlap writes same vals

    const float2* __restrict__ inp = (const float2*)(x + (size_t)img * H * W);

    // ---- initial vertical window: rows [r0, r0+99]
    float a0 = 0.f, a1 = 0.f;
    #pragma unroll 4
    for (int k = 0; k < KS; ++k) {
        float2 v = inp[(size_t)(r0 + k) * W2 + tid];
        a0 += v.x; a1 += v.y;
    }

    float acc0[4], acc1[4];
    acc0[0] = a0; acc1[0] = a1;
    // rows r0+1 .. r0+3
    {
        float2 ca[3], cs[3];
        #pragma unroll
        for (int i = 0; i < 3; ++i) {
            ca[i] = inp[(size_t)(r0 + KS + i) * W2 + tid];
            cs[i] = inp[(size_t)(r0 + i) * W2 + tid];
        }
        #pragma unroll
        for (int i = 0; i < 3; ++i) {
            a0 += ca[i].x - cs[i].x;
            a1 += ca[i].y - cs[i].y;
            acc0[i + 1] = a0; acc1[i + 1] = a1;
        }
    }

    for (int g = 0; g < NG; ++g) {
        const int rg = r0 + 4 * g;

        // ---- prefetch next group's add/sub rows (overlaps scan below)
        float2 na[4], ns[4];
        const bool more = (g + 1 < NG);
        if (more) {
            #pragma unroll
            for (int i = 0; i < 4; ++i) {
                na[i] = inp[(size_t)(rg + 103 + i) * W2 + tid];
                ns[i] = inp[(size_t)(rg + 3 + i) * W2 + tid];
            }
        }

        // ---- 4 concurrent block prefix scans over the vertical sums
        float p1[4], t[4];
        #pragma unroll
        for (int i = 0; i < 4; ++i) { p1[i] = acc0[i] + acc1[i]; t[i] = p1[i]; }

        #pragma unroll
        for (int d = 1; d < 32; d <<= 1) {
            float n0 = __shfl_up_sync(0xffffffffu, t[0], d);
            float n1 = __shfl_up_sync(0xffffffffu, t[1], d);
            float n2 = __shfl_up_sync(0xffffffffu, t[2], d);
            float n3 = __shfl_up_sync(0xffffffffu, t[3], d);
            if (lane >= d) { t[0] += n0; t[1] += n1; t[2] += n2; t[3] += n3; }
        }
        if (lane == 31) {
            #pragma unroll
            for (int i = 0; i < 4; ++i) warpsum[i][warp] = t[i];
        }
        __syncthreads();

        if (warp < 4) {   // warp i scans row i's 16 warp totals
            float wv = (lane < NT / 32) ? warpsum[warp][lane] : 0.f;
            #pragma unroll
            for (int d = 1; d < NT / 32; d <<= 1) {
                float n = __shfl_up_sync(0xffffffffu, wv, d);
                if (lane >= d) wv += n;
            }
            if (lane < NT / 32) warpsum[warp][lane] = wv;
        }
        __syncthreads();

        #pragma unroll
        for (int i = 0; i < 4; ++i) {
            float base = (warp ? warpsum[i][warp - 1] : 0.f) + (t[i] - p1[i]);
            sp[i][2 * tid + 0] = base + acc0[i];
            sp[i][2 * tid + 1] = base + p1[i];
        }
        __syncthreads();

        // ---- horizontal 100-sum by prefix difference, scale, threshold
        #pragma unroll
        for (int i = 0; i < 4; ++i) {
            float* __restrict__ orow = out + ((size_t)img * OH + rg + i) * OW;
            #pragma unroll
            for (int j = tid; j < OW; j += NT) {
                float s = sp[i][j + KS - 1] - (j ? sp[i][j - 1] : 0.f);
                float o = s * 1e-4f;
                orow[j] = (o > 0.129f) ? 1.0f : o;
            }
        }
        __syncthreads();   // sp/warpsum reused next group

        // ---- advance accumulators for rows rg+4 .. rg+7
        if (more) {
            #pragma unroll
            for (int i = 0; i < 4; ++i) {
                a0 += na[i].x - ns[i].x;
                a1 += na[i].y - ns[i].y;
                acc0[i] = a0; acc1[i] = a1;
            }
        }
    }
}

extern "C" void kernel_launch(void* const* d_in, const int* in_sizes, int n_in,
                              void* d_out, int out_size) {
    (void)in_sizes; (void)n_in; (void)out_size;
    const float* x = (const float*)d_in[0];
    float* out     = (float*)d_out;

    dim3 grid(NCHUNK, IMGS);     // 13 x 24 = 312 blocks
    blur_fused4<<<grid, NT>>>(x, out);
}

// round 6
// speedup vs baseline: 1.5105x; 1.2086x over previous
#include <cuda_runtime.h>

// BlurModel: 100x100 box filter (x 1e-4), VALID, threshold >0.129 -> 1.0.
// Input  x: [8,3,1024,1024] f32 (24 images), output [8,3,925,925] f32.
//
// Fused separable filter:
//   - 288 blocks (12 row-chunks x 24 images) == exactly 2 per SM, balanced
//   - vertical sliding 100-sums in registers (2 cols/thread, 512 threads)
//   - 5 output rows per scan group: 5 concurrent block prefix scans
//   - double-buffered smem prefixes -> 3 barriers per 5 rows
//   - horizontal 100-sum by prefix difference, scale, threshold, store

#define IMGS   24
#define H      1024
#define W      1024
#define W2     (W / 2)
#define KS     100
#define OH     925
#define OW     925
#define RC     80           // rows per block
#define G      5            // rows per scan group
#define NG     (RC / G)     // 16 groups
#define NCHUNK 12
#define NT     512
#define NW     (NT / 32)    // 16 warps

__global__ __launch_bounds__(NT, 2) void blur_fused5(const float* __restrict__ x,
                                                     float* __restrict__ out) {
    __shared__ float sp[2][G][W];        // double-buffered row prefixes, 40 KB
    __shared__ float warpsum[2][G][NW];  // 640 B

    const int tid  = threadIdx.x;
    const int lane = tid & 31;
    const int warp = tid >> 5;
    const int img  = blockIdx.y;
    int r0 = blockIdx.x * RC;
    if (r0 > OH - RC) r0 = OH - RC;      // uniform chunks; overlap rows identical

    const float2* __restrict__ inp = (const float2*)(x + (size_t)img * H * W);

    // ---- initial vertical window: rows [r0, r0+99]
    float a0 = 0.f, a1 = 0.f;
    #pragma unroll 10
    for (int k = 0; k < KS; ++k) {
        float2 v = inp[(size_t)(r0 + k) * W2 + tid];
        a0 += v.x; a1 += v.y;
    }

    float acc0[G], acc1[G];
    acc0[0] = a0; acc1[0] = a1;
    {   // rows r0+1 .. r0+4 (sub rows are cache-warm from the init loop)
        float2 ca[G - 1], cs[G - 1];
        #pragma unroll
        for (int i = 0; i < G - 1; ++i) {
            ca[i] = inp[(size_t)(r0 + KS + i) * W2 + tid];
            cs[i] = inp[(size_t)(r0 + i) * W2 + tid];
        }
        #pragma unroll
        for (int i = 0; i < G - 1; ++i) {
            a0 += ca[i].x - cs[i].x;
            a1 += ca[i].y - cs[i].y;
            acc0[i + 1] = a0; acc1[i + 1] = a1;
        }
    }

    for (int g = 0; g < NG; ++g) {
        const int rg  = r0 + G * g;
        const int buf = g & 1;

        // ---- prefetch next group's add/sub rows (in flight during the scans)
        float2 na[G], ns[G];
        const bool more = (g + 1 < NG);
        if (more) {
            #pragma unroll
            for (int i = 0; i < G; ++i) {
                na[i] = inp[(size_t)(rg + KS + G - 1 + i) * W2 + tid]; // rg+104+i
                ns[i] = inp[(size_t)(rg + G - 1 + i) * W2 + tid];      // rg+4+i
            }
        }

        // ---- G concurrent block prefix scans over the vertical sums
        float t[G];
        #pragma unroll
        for (int i = 0; i < G; ++i) t[i] = acc0[i] + acc1[i];

        #pragma unroll
        for (int d = 1; d < 32; d <<= 1) {
            float n[G];
            #pragma unroll
            for (int i = 0; i < G; ++i) n[i] = __shfl_up_sync(0xffffffffu, t[i], d);
            if (lane >= d) {
                #pragma unroll
                for (int i = 0; i < G; ++i) t[i] += n[i];
            }
        }
        if (lane == 31) {
            #pragma unroll
            for (int i = 0; i < G; ++i) warpsum[buf][i][warp] = t[i];
        }
        __syncthreads();

        if (warp < G) {   // warp i scans row i's 16 warp totals
            float wv = (lane < NW) ? warpsum[buf][warp][lane] : 0.f;
            #pragma unroll
            for (int d = 1; d < NW; d <<= 1) {
                float n = __shfl_up_sync(0xffffffffu, wv, d);
                if (lane >= d) wv += n;
            }
            if (lane < NW) warpsum[buf][warp][lane] = wv;
        }
        __syncthreads();

        #pragma unroll
        for (int i = 0; i < G; ++i) {
            float p1   = acc0[i] + acc1[i];
            float base = (warp ? warpsum[buf][i][warp - 1] : 0.f) + (t[i] - p1);
            sp[buf][i][2 * tid + 0] = base + acc0[i];
            sp[buf][i][2 * tid + 1] = base + p1;
        }
        __syncthreads();

        // ---- horizontal 100-sum by prefix difference, scale, threshold
        #pragma unroll
        for (int i = 0; i < G; ++i) {
            float* __restrict__ orow = out + ((size_t)img * OH + rg + i) * OW;
            #pragma unroll
            for (int j = tid; j < OW; j += NT) {
                float s = sp[buf][i][j + KS - 1] - (j ? sp[buf][i][j - 1] : 0.f);
                float o = s * 1e-4f;
                orow[j] = (o > 0.129f) ? 1.0f : o;
            }
        }
        // no trailing barrier: next group uses the other sp/warpsum buffer

        // ---- advance accumulators for rows rg+5 .. rg+9
        if (more) {
            #pragma unroll
            for (int i = 0; i < G; ++i) {
                a0 += na[i].x - ns[i].x;
                a1 += na[i].y - ns[i].y;
                acc0[i] = a0; acc1[i] = a1;
            }
        }
    }
}

extern "C" void kernel_launch(void* const* d_in, const int* in_sizes, int n_in,
                              void* d_out, int out_size) {
    (void)in_sizes; (void)n_in; (void)out_size;
    const float* x = (const float*)d_in[0];
    float* out     = (float*)d_out;

    dim3 grid(NCHUNK, IMGS);     // 12 x 24 = 288 blocks = 2/SM on 148 SMs
    blur_fused5<<<grid, NT>>>(x, out);
}